// round 14
// baseline (speedup 1.0000x reference)
#include <cuda_runtime.h>
#include <math.h>

#define B 32
#define N 512
#define FIN 16
#define H 8
#define DH 8
#define DOUT 32
#define LOG2E 1.4426950408889634f

typedef unsigned long long ull;
typedef unsigned short u16;

// ---------------- scratch ----------------
__device__ float g_Wh[B*N*H*DH];          // [b][n][h*8+d]
__device__ float g_f1[B*N*H];             // [b][n][h]  (prescaled by log2e)
__device__ float g_f2[B*N*H];             // [b][n][h]  (prescaled by log2e)
__device__ float g_Who[B*N*DOUT];         // [b][n][d]
__device__ float g_g1[B*N];               // prescaled by log2e
__device__ float g_g2[B*N];               // prescaled by log2e
__device__ float g_outT[N*DOUT*B];        // [k][b], k = n*32+d
__device__ float g_qpart[128*B*N];        // split-K partials
__device__ int   g_cnt[B*N];
__device__ u16   g_nbr[B*N*N];            // compacted neighbor lists (16-bit)

// ---------------- helpers ----------------
__device__ __forceinline__ float lrelu(float x){ return fmaxf(x, 0.2f*x); }
__device__ __forceinline__ float elu(float x){ return x > 0.f ? x : expm1f(x); }
__device__ __forceinline__ float ex2f(float x){
    float r; asm("ex2.approx.ftz.f32 %0, %1;" : "=f"(r) : "f"(x)); return r;
}
__device__ __forceinline__ ull fma2(ull a, ull b, ull c){
    ull d;
    asm("fma.rn.f32x2 %0, %1, %2, %3;" : "=l"(d) : "l"(a), "l"(b), "l"(c));
    return d;
}
__device__ __forceinline__ ull pack2(float x){
    ull r;
    asm("mov.b64 %0, {%1, %1};" : "=l"(r) : "f"(x));
    return r;
}
__device__ __forceinline__ void unpack2(ull v, float& lo, float& hi){
    asm("mov.b64 {%0, %1}, %2;" : "=f"(lo), "=f"(hi) : "l"(v));
}

// ---------------- K0: compact adjacency rows into 16-bit neighbor lists ----------------
__global__ void k0_compact(const float* __restrict__ adj){
    int t = threadIdx.x, w = t >> 5, lane = t & 31;
    int row = blockIdx.x * 8 + w;
    const float* arow = adj + (size_t)row * N;
    float av[16];
#pragma unroll
    for (int c = 0; c < 16; c++) av[c] = arow[c*32 + lane];
    unsigned bal[16];
#pragma unroll
    for (int c = 0; c < 16; c++) bal[c] = __ballot_sync(0xffffffffu, av[c] > 0.f);
    u16* dst = g_nbr + (size_t)row * N;
    int base = 0;
    unsigned lmask = (1u << lane) - 1u;
#pragma unroll
    for (int c = 0; c < 16; c++){
        unsigned b = bal[c];
        if ((b >> lane) & 1u) dst[base + __popc(b & lmask)] = (u16)(c*32 + lane);
        base += __popc(b);
    }
    if (lane == 0) g_cnt[row] = base;
}

// ---------------- K1: Wh = xv @ W_heads ; f1 ; f2 (f1/f2 prescaled by log2e) ----------------
__global__ void k1_proj(const float* __restrict__ xv,
                        const float* __restrict__ Wheads,
                        const float* __restrict__ a1,
                        const float* __restrict__ a2){
    __shared__ float Ws[H*FIN*DH];
    __shared__ float a1s[H*DH], a2s[H*DH];
    int t = threadIdx.x;
    for (int i = t; i < H*FIN*DH; i += 256) Ws[i] = Wheads[i];
    if (t < H*DH){ a1s[t] = a1[t]; a2s[t] = a2[t]; }
    __syncthreads();

    int gt = blockIdx.x * 256 + t;
    int h  = gt & 7;
    int bn = gt >> 3;
    const float* xr = xv + bn * FIN;

    float wh[DH];
#pragma unroll
    for (int d = 0; d < DH; d++) wh[d] = 0.f;
#pragma unroll
    for (int f = 0; f < FIN; f++){
        float x = xr[f];
        const float* wf = Ws + (h*FIN + f)*DH;
#pragma unroll
        for (int d = 0; d < DH; d++) wh[d] += x * wf[d];
    }
    float f1v = 0.f, f2v = 0.f;
#pragma unroll
    for (int d = 0; d < DH; d++){
        f1v += wh[d] * a1s[h*DH + d];
        f2v += wh[d] * a2s[h*DH + d];
    }
    float* dstp = g_Wh + (size_t)bn*64 + h*8;
    ((float4*)dstp)[0] = make_float4(wh[0], wh[1], wh[2], wh[3]);
    ((float4*)dstp)[1] = make_float4(wh[4], wh[5], wh[6], wh[7]);
    g_f1[bn*8 + h] = f1v * LOG2E;
    g_f2[bn*8 + h] = f2v * LOG2E;
}

// ---------------- K2: fused layer-1 attention + Who GEMM + g1/g2 ----------------
// 4 rows/block; each row = 2 warps (warp covers 4 heads x 8 dims).
// Phase A: one score per lane -> smem {p, byteoff}; Phase B: pure gather-FMA.
__global__ void k2_fused(const float* __restrict__ Wout,
                         const float* __restrict__ a1o,
                         const float* __restrict__ a2o){
    __shared__ float  Ws[64*32];       // 8 KB
    __shared__ float  hs[4][64];
    __shared__ float2 ps[8][8][4];     // [warp][k8][hh]
    __shared__ float  a1s[32], a2s[32];
    int t = threadIdx.x;
    for (int i = t; i < 64*32; i += 256) Ws[i] = Wout[i];
    if (t < 32){ a1s[t] = a1o[t]; a2s[t] = a2o[t]; }

    int g = t >> 6, u = t & 63;
    int wIdx = t >> 5, lane = t & 31;
    int hbase = (wIdx & 1) * 4;
    int row = blockIdx.x * 4 + g;
    int b = row >> 9;

    int cnt = g_cnt[row];
    const u16* __restrict__ jl = g_nbr + (size_t)row * N;
    const float* __restrict__ f2B = g_f2 + (size_t)b * N * 8;
    const float* __restrict__ WhB = g_Wh + (size_t)b * N * 64;

    // phase-A assignment: lane = k8*4 + hh
    int k8 = lane >> 2, hh = lane & 3;
    int hA = hbase + hh;
    float f1A = g_f1[row*8 + hA];
    int hl = lane >> 3;                 // head-within-warp for phase B

    float s = 0.f, acc = 0.f;
    if (cnt > 0){
        for (int base = 0; base < cnt; base += 8){
            float p = 0.f; int off = 0;
            int kk = base + k8;
            if (kk < cnt){
                int j = (int)jl[kk];
                off = j * 64;
                float e = f1A + f2B[j*8 + hA];
                p = ex2f(lrelu(e));
            }
            ps[wIdx][k8][hh] = make_float2(p, __int_as_float(off));
            __syncwarp();
            int lim = min(8, cnt - base);
#pragma unroll 8
            for (int q = 0; q < lim; q++){
                float2 pj = ps[wIdx][q][hl];
                float pv = pj.x;
                int  o   = __float_as_int(pj.y);
                s += pv;
                acc += pv * WhB[o + u];
            }
            __syncwarp();
        }
    } else {
        s = (float)N;
        for (int j = 0; j < N; j++) acc += WhB[j*64 + u];
    }
    hs[g][u] = elu(acc / s);
    __syncthreads();

    // phase 2: Who[row][c] (first warp of each row's thread pair)
    if (u < 32){
        int c = u;
        const float* hrow = hs[g];
        float who = 0.f;
#pragma unroll
        for (int f = 0; f < 64; f++) who += hrow[f] * Ws[f*32 + c];
        g_Who[(size_t)row*32 + c] = who;
        float v1 = who * a1s[c], v2 = who * a2s[c];
#pragma unroll
        for (int o = 16; o; o >>= 1){
            v1 += __shfl_xor_sync(0xffffffffu, v1, o);
            v2 += __shfl_xor_sync(0xffffffffu, v2, o);
        }
        if (c == 0){ g_g1[row] = v1 * LOG2E; g_g2[row] = v2 * LOG2E; }
    }
}

// ---------------- K4: layer-2 attention, warp/row, two-phase scoring ----------------
__global__ void k4_outattn(){
    __shared__ float2 ps[8][32];
    int t = threadIdx.x, w = t >> 5, lane = t & 31;
    int row = blockIdx.x * 8 + w;       // = b*512 + i
    int b = row >> 9, i = row & 511;
    int cnt = g_cnt[row];
    const u16* __restrict__ jl = g_nbr + (size_t)row * N;

    float g1i = g_g1[row];
    const float* __restrict__ g2b  = g_g2 + b * N;
    const float* __restrict__ WhoB = g_Who + (size_t)b * N * DOUT;

    float s = 0.f, tot = 0.f;
    if (cnt > 0){
        for (int base = 0; base < cnt; base += 32){
            float p = 0.f; int off = 0;
            int kk = base + lane;
            if (kk < cnt){
                int j = (int)jl[kk];
                off = j * 32;
                float e = g1i + g2b[j];
                p = ex2f(lrelu(e));
            }
            ps[w][lane] = make_float2(p, __int_as_float(off));
            __syncwarp();
            int lim = min(32, cnt - base);
#pragma unroll 8
            for (int q = 0; q < lim; q++){
                float2 pj = ps[w][q];
                float pv = pj.x;
                int  o   = __float_as_int(pj.y);
                s += pv;
                tot += pv * WhoB[o + lane];
            }
            __syncwarp();
        }
    } else {
        s = (float)N;
        for (int j = 0; j < N; j++) tot += WhoB[j*32 + lane];
    }
    g_outT[(size_t)(i*32 + lane)*B + b] = elu(tot / s);
}

// ---------------- K5: register-tiled GEMM  q = out[32,16384] @ Wq[16384,512] ----------------
__global__ void k5_qgemm(const float* __restrict__ Wq){
    __shared__ float outS[64*32];   // [k][b]  8 KB
    __shared__ float wqS[64*64];    // [k][c] 16 KB
    int t = threadIdx.x;
    int slice = t >> 6;             // 0..3
    int u = t & 63;
    int tx = u & 7;
    int ty = u >> 3;
    int b0 = ty*4, c0 = tx*8;
    int cb = blockIdx.x;
    int ky = blockIdx.y;
    int k0blk = ky * 512;

    ull acc2[16];
#pragma unroll
    for (int q = 0; q < 16; q++) acc2[q] = 0ull;

    for (int st = 0; st < 8; st++){
        int k0 = k0blk + st*64;
        __syncthreads();
        {
            const float4* src = (const float4*)(g_outT + (size_t)k0*32);
            float4* dst = (float4*)outS;
            dst[t]       = src[t];
            dst[t + 256] = src[t + 256];
        }
#pragma unroll
        for (int i = 0; i < 4; i++){
            int lin = t + i*256;
            int kk = lin >> 4;
            int cq = lin & 15;
            ((float4*)wqS)[kk*16 + cq] =
                *(const float4*)(Wq + (size_t)(k0 + kk)*512 + cb*64 + cq*4);
        }
        __syncthreads();

        const float* oS = outS + slice*16*32;
        const float* wS = wqS  + slice*16*64;
#pragma unroll
        for (int kk = 0; kk < 16; kk++){
            float4 o4 = *(const float4*)(oS + kk*32 + b0);
            ull ob0 = pack2(o4.x), ob1 = pack2(o4.y), ob2 = pack2(o4.z), ob3 = pack2(o4.w);
            const ull* w2 = (const ull*)(wS + kk*64 + c0);
#pragma unroll
            for (int cp = 0; cp < 4; cp++){
                ull wv = w2[cp];
                acc2[0*4+cp] = fma2(ob0, wv, acc2[0*4+cp]);
                acc2[1*4+cp] = fma2(ob1, wv, acc2[1*4+cp]);
                acc2[2*4+cp] = fma2(ob2, wv, acc2[2*4+cp]);
                acc2[3*4+cp] = fma2(ob3, wv, acc2[3*4+cp]);
            }
        }
    }
    float* qp = g_qpart + (size_t)(ky*4 + slice) * (B*N);
#pragma unroll
    for (int bb = 0; bb < 4; bb++)
#pragma unroll
        for (int cp = 0; cp < 4; cp++){
            float lo, hi; unpack2(acc2[bb*4+cp], lo, hi);
            int c = cb*64 + c0 + cp*2;
            qp[(b0+bb)*N + c]     = lo;
            qp[(b0+bb)*N + c + 1] = hi;
        }
}

// ---------------- K6: q = sum of 128 partials + b_q (float4) ----------------
__global__ void k6_reduce(const float* __restrict__ bq, float* __restrict__ q){
    int t4 = blockIdx.x * 128 + threadIdx.x;   // [0, 4096)
    int c4 = t4 & 127;
    float4 s = ((const float4*)bq)[c4];
#pragma unroll
    for (int p = 0; p < 128; p++){
        float4 v = ((const float4*)(g_qpart + (size_t)p*(B*N)))[t4];
        s.x += v.x; s.y += v.y; s.z += v.z; s.w += v.w;
    }
    ((float4*)q)[t4] = s;
}

// ---------------- launch ----------------
extern "C" void kernel_launch(void* const* d_in, const int* in_sizes, int n_in,
                              void* d_out, int out_size){
    const float* xv    = (const float*)d_in[0];
    const float* adj   = (const float*)d_in[1];
    const float* Whead = (const float*)d_in[2];
    const float* a1    = (const float*)d_in[3];
    const float* a2    = (const float*)d_in[4];
    const float* Wout  = (const float*)d_in[5];
    const float* a1o   = (const float*)d_in[6];
    const float* a2o   = (const float*)d_in[7];
    const float* Wq    = (const float*)d_in[8];
    const float* bq    = (const float*)d_in[9];
    float* q = (float*)d_out;

    k0_compact<<<B*N/8, 256>>>(adj);
    k1_proj   <<<512, 256>>>(xv, Whead, a1, a2);
    k2_fused  <<<B*N/4, 256>>>(Wout, a1o, a2o);
    k4_outattn<<<B*N/8, 256>>>();
    k5_qgemm  <<<dim3(8, 32), 256>>>(Wq);
    k6_reduce <<<32, 128>>>(bq, q);
}

// round 15
// speedup vs baseline: 1.0992x; 1.0992x over previous
#include <cuda_runtime.h>
#include <math.h>

#define B 32
#define N 512
#define FIN 16
#define H 8
#define DH 8
#define DOUT 32
#define LOG2E 1.4426950408889634f

typedef unsigned long long ull;
typedef unsigned short u16;

// ---------------- scratch ----------------
__device__ float g_Wh[B*N*H*DH];          // [b][n][h*8+d]
__device__ float g_f1[B*N*H];             // [b][n][h]  (prescaled by log2e)
__device__ float g_f2[B*N*H];             // [b][n][h]  (prescaled by log2e)
__device__ float g_Who[B*N*DOUT];         // [b][n][d]
__device__ float g_g1[B*N];               // prescaled by log2e
__device__ float g_g2[B*N];               // prescaled by log2e
__device__ float g_outT[N*DOUT*B];        // [k][b], k = n*32+d
__device__ float g_qpart[128*B*N];        // split-K partials
__device__ int   g_cnt[B*N];
__device__ u16   g_nbr[B*N*N];            // compacted neighbor lists (16-bit)

// ---------------- helpers ----------------
__device__ __forceinline__ float lrelu(float x){ return fmaxf(x, 0.2f*x); }
__device__ __forceinline__ float elu(float x){ return x > 0.f ? x : expm1f(x); }
__device__ __forceinline__ float ex2f(float x){
    float r; asm("ex2.approx.ftz.f32 %0, %1;" : "=f"(r) : "f"(x)); return r;
}
__device__ __forceinline__ ull fma2(ull a, ull b, ull c){
    ull d;
    asm("fma.rn.f32x2 %0, %1, %2, %3;" : "=l"(d) : "l"(a), "l"(b), "l"(c));
    return d;
}
__device__ __forceinline__ ull pack2(float x){
    ull r;
    asm("mov.b64 %0, {%1, %1};" : "=l"(r) : "f"(x));
    return r;
}
__device__ __forceinline__ void unpack2(ull v, float& lo, float& hi){
    asm("mov.b64 {%0, %1}, %2;" : "=f"(lo), "=f"(hi) : "l"(v));
}

// ---------------- K0: compact adjacency rows into 16-bit neighbor lists ----------------
__global__ void k0_compact(const float* __restrict__ adj){
    int t = threadIdx.x, w = t >> 5, lane = t & 31;
    int row = blockIdx.x * 8 + w;
    const float* arow = adj + (size_t)row * N;
    float av[16];
#pragma unroll
    for (int c = 0; c < 16; c++) av[c] = arow[c*32 + lane];
    unsigned bal[16];
#pragma unroll
    for (int c = 0; c < 16; c++) bal[c] = __ballot_sync(0xffffffffu, av[c] > 0.f);
    u16* dst = g_nbr + (size_t)row * N;
    int base = 0;
    unsigned lmask = (1u << lane) - 1u;
#pragma unroll
    for (int c = 0; c < 16; c++){
        unsigned b = bal[c];
        if ((b >> lane) & 1u) dst[base + __popc(b & lmask)] = (u16)(c*32 + lane);
        base += __popc(b);
    }
    if (lane == 0) g_cnt[row] = base;
}

// ---------------- K1: Wh = xv @ W_heads ; f1 ; f2 (prescaled by log2e) ----------------
__global__ void k1_proj(const float* __restrict__ xv,
                        const float* __restrict__ Wheads,
                        const float* __restrict__ a1,
                        const float* __restrict__ a2){
    __shared__ float Ws[H*FIN*DH];
    __shared__ float a1s[H*DH], a2s[H*DH];
    int t = threadIdx.x;
    for (int i = t; i < H*FIN*DH; i += 256) Ws[i] = Wheads[i];
    if (t < H*DH){ a1s[t] = a1[t]; a2s[t] = a2[t]; }
    __syncthreads();

    int gt = blockIdx.x * 256 + t;
    int h  = gt & 7;
    int bn = gt >> 3;
    const float* xr = xv + bn * FIN;

    float wh[DH];
#pragma unroll
    for (int d = 0; d < DH; d++) wh[d] = 0.f;
#pragma unroll
    for (int f = 0; f < FIN; f++){
        float x = xr[f];
        const float* wf = Ws + (h*FIN + f)*DH;
#pragma unroll
        for (int d = 0; d < DH; d++) wh[d] += x * wf[d];
    }
    float f1v = 0.f, f2v = 0.f;
#pragma unroll
    for (int d = 0; d < DH; d++){
        f1v += wh[d] * a1s[h*DH + d];
        f2v += wh[d] * a2s[h*DH + d];
    }
    float* dstp = g_Wh + (size_t)bn*64 + h*8;
    ((float4*)dstp)[0] = make_float4(wh[0], wh[1], wh[2], wh[3]);
    ((float4*)dstp)[1] = make_float4(wh[4], wh[5], wh[6], wh[7]);
    g_f1[bn*8 + h] = f1v * LOG2E;
    g_f2[bn*8 + h] = f2v * LOG2E;
}

// ---------------- K2: fused layer-1 attention + Who GEMM + g1/g2 (direct scoring) ----------------
__global__ void k2_fused(const float* __restrict__ Wout,
                         const float* __restrict__ a1o,
                         const float* __restrict__ a2o){
    __shared__ float Ws[64*32];     // 8 KB
    __shared__ float hs[4][64];
    __shared__ float a1s[32], a2s[32];
    int t = threadIdx.x;
    for (int i = t; i < 64*32; i += 256) Ws[i] = Wout[i];
    if (t < 32){ a1s[t] = a1o[t]; a2s[t] = a2o[t]; }

    int g = t >> 6, u = t & 63;
    int h = u >> 3;
    int row = blockIdx.x * 4 + g;
    int b = row >> 9;

    int cnt = g_cnt[row];
    const u16* __restrict__ jl = g_nbr + (size_t)row * N;
    const float* __restrict__ f2B = g_f2 + (size_t)b * N * 8;
    const float* __restrict__ WhB = g_Wh + (size_t)b * N * 64;
    float f1i = g_f1[row*8 + h];

    float s = 0.f, acc = 0.f;
    if (cnt > 0){
        int k = 0;
        for (; k + 8 <= cnt; k += 8){
            uint4 v = *(const uint4*)(jl + k);
            int o0 = (v.x & 0xFFFF)*64, o1 = (v.x >> 16)*64;
            int o2 = (v.y & 0xFFFF)*64, o3 = (v.y >> 16)*64;
            int o4 = (v.z & 0xFFFF)*64, o5 = (v.z >> 16)*64;
            int o6 = (v.w & 0xFFFF)*64, o7 = (v.w >> 16)*64;
            float e0 = f2B[(o0>>3) + h], e1 = f2B[(o1>>3) + h];
            float e2 = f2B[(o2>>3) + h], e3 = f2B[(o3>>3) + h];
            float e4 = f2B[(o4>>3) + h], e5 = f2B[(o5>>3) + h];
            float e6 = f2B[(o6>>3) + h], e7 = f2B[(o7>>3) + h];
            float w0 = WhB[o0 + u], w1 = WhB[o1 + u];
            float w2 = WhB[o2 + u], w3 = WhB[o3 + u];
            float w4 = WhB[o4 + u], w5 = WhB[o5 + u];
            float w6 = WhB[o6 + u], w7 = WhB[o7 + u];
            float p0 = ex2f(lrelu(f1i + e0)), p1 = ex2f(lrelu(f1i + e1));
            float p2 = ex2f(lrelu(f1i + e2)), p3 = ex2f(lrelu(f1i + e3));
            float p4 = ex2f(lrelu(f1i + e4)), p5 = ex2f(lrelu(f1i + e5));
            float p6 = ex2f(lrelu(f1i + e6)), p7 = ex2f(lrelu(f1i + e7));
            s += p0; s += p1; s += p2; s += p3;
            s += p4; s += p5; s += p6; s += p7;
            acc += p0*w0; acc += p1*w1; acc += p2*w2; acc += p3*w3;
            acc += p4*w4; acc += p5*w5; acc += p6*w6; acc += p7*w7;
        }
        for (; k < cnt; k++){
            int j = (int)jl[k];
            float p = ex2f(lrelu(f1i + f2B[j*8 + h]));
            s += p;
            acc += p * WhB[j*64 + u];
        }
    } else {
        s = (float)N;
        for (int j = 0; j < N; j++) acc += WhB[j*64 + u];
    }
    hs[g][u] = elu(acc / s);
    __syncthreads();

    // phase 2: Who[row][c]
    if (u < 32){
        int c = u;
        const float* hrow = hs[g];
        float who = 0.f;
#pragma unroll
        for (int f = 0; f < 64; f++) who += hrow[f] * Ws[f*32 + c];
        g_Who[(size_t)row*32 + c] = who;
        float v1 = who * a1s[c], v2 = who * a2s[c];
#pragma unroll
        for (int o = 16; o; o >>= 1){
            v1 += __shfl_xor_sync(0xffffffffu, v1, o);
            v2 += __shfl_xor_sync(0xffffffffu, v2, o);
        }
        if (c == 0){ g_g1[row] = v1 * LOG2E; g_g2[row] = v2 * LOG2E; }
    }
}

// ---------------- K4: layer-2 attention, lane=dim, direct scoring, chunk-16 ----------------
__global__ void k4_outattn(){
    int t = threadIdx.x, w = t >> 5, lane = t & 31;
    int row = blockIdx.x * 8 + w;       // = b*512 + i
    int b = row >> 9, i = row & 511;
    int cnt = g_cnt[row];
    const u16* __restrict__ jl = g_nbr + (size_t)row * N;

    float g1i = g_g1[row];
    const float* __restrict__ g2b  = g_g2 + b * N;
    const float* __restrict__ WhoB = g_Who + (size_t)b * N * DOUT;

    float s = 0.f, tot = 0.f;
    if (cnt > 0){
        int k = 0;
        for (; k + 16 <= cnt; k += 16){
            uint4 va = *(const uint4*)(jl + k);
            uint4 vb = *(const uint4*)(jl + k + 8);
            int j0 = va.x & 0xFFFF, j1 = va.x >> 16, j2 = va.y & 0xFFFF, j3 = va.y >> 16;
            int j4 = va.z & 0xFFFF, j5 = va.z >> 16, j6 = va.w & 0xFFFF, j7 = va.w >> 16;
            int j8 = vb.x & 0xFFFF, j9 = vb.x >> 16, jA = vb.y & 0xFFFF, jB = vb.y >> 16;
            int jC = vb.z & 0xFFFF, jD = vb.z >> 16, jE = vb.w & 0xFFFF, jF = vb.w >> 16;
            float e0 = g2b[j0], e1 = g2b[j1], e2 = g2b[j2], e3 = g2b[j3];
            float e4 = g2b[j4], e5 = g2b[j5], e6 = g2b[j6], e7 = g2b[j7];
            float e8 = g2b[j8], e9 = g2b[j9], eA = g2b[jA], eB = g2b[jB];
            float eC = g2b[jC], eD = g2b[jD], eE = g2b[jE], eF = g2b[jF];
            float w0 = WhoB[j0*32 + lane], w1 = WhoB[j1*32 + lane];
            float w2 = WhoB[j2*32 + lane], w3 = WhoB[j3*32 + lane];
            float w4 = WhoB[j4*32 + lane], w5 = WhoB[j5*32 + lane];
            float w6 = WhoB[j6*32 + lane], w7 = WhoB[j7*32 + lane];
            float w8 = WhoB[j8*32 + lane], w9 = WhoB[j9*32 + lane];
            float wA = WhoB[jA*32 + lane], wB = WhoB[jB*32 + lane];
            float wC = WhoB[jC*32 + lane], wD = WhoB[jD*32 + lane];
            float wE = WhoB[jE*32 + lane], wF = WhoB[jF*32 + lane];
            float p0 = ex2f(lrelu(g1i + e0)), p1 = ex2f(lrelu(g1i + e1));
            float p2 = ex2f(lrelu(g1i + e2)), p3 = ex2f(lrelu(g1i + e3));
            float p4 = ex2f(lrelu(g1i + e4)), p5 = ex2f(lrelu(g1i + e5));
            float p6 = ex2f(lrelu(g1i + e6)), p7 = ex2f(lrelu(g1i + e7));
            float p8 = ex2f(lrelu(g1i + e8)), p9 = ex2f(lrelu(g1i + e9));
            float pA = ex2f(lrelu(g1i + eA)), pB = ex2f(lrelu(g1i + eB));
            float pC = ex2f(lrelu(g1i + eC)), pD = ex2f(lrelu(g1i + eD));
            float pE = ex2f(lrelu(g1i + eE)), pF = ex2f(lrelu(g1i + eF));
            s += p0; s += p1; s += p2; s += p3; s += p4; s += p5; s += p6; s += p7;
            s += p8; s += p9; s += pA; s += pB; s += pC; s += pD; s += pE; s += pF;
            tot += p0*w0; tot += p1*w1; tot += p2*w2; tot += p3*w3;
            tot += p4*w4; tot += p5*w5; tot += p6*w6; tot += p7*w7;
            tot += p8*w8; tot += p9*w9; tot += pA*wA; tot += pB*wB;
            tot += pC*wC; tot += pD*wD; tot += pE*wE; tot += pF*wF;
        }
        for (; k < cnt; k++){
            int j = (int)jl[k];
            float p = ex2f(lrelu(g1i + g2b[j]));
            s += p;
            tot += p * WhoB[j*32 + lane];
        }
    } else {
        s = (float)N;
        for (int j = 0; j < N; j++) tot += WhoB[j*32 + lane];
    }
    g_outT[(size_t)(i*32 + lane)*B + b] = elu(tot / s);
}

// ---------------- K5: register-tiled GEMM  q = out[32,16384] @ Wq[16384,512] ----------------
__global__ void k5_qgemm(const float* __restrict__ Wq){
    __shared__ float outS[64*32];   // [k][b]  8 KB
    __shared__ float wqS[64*64];    // [k][c] 16 KB
    int t = threadIdx.x;
    int slice = t >> 6;             // 0..3
    int u = t & 63;
    int tx = u & 7;
    int ty = u >> 3;
    int b0 = ty*4, c0 = tx*8;
    int cb = blockIdx.x;
    int ky = blockIdx.y;
    int k0blk = ky * 512;

    ull acc2[16];
#pragma unroll
    for (int q = 0; q < 16; q++) acc2[q] = 0ull;

    for (int st = 0; st < 8; st++){
        int k0 = k0blk + st*64;
        __syncthreads();
        {
            const float4* src = (const float4*)(g_outT + (size_t)k0*32);
            float4* dst = (float4*)outS;
            dst[t]       = src[t];
            dst[t + 256] = src[t + 256];
        }
#pragma unroll
        for (int i = 0; i < 4; i++){
            int lin = t + i*256;
            int kk = lin >> 4;
            int cq = lin & 15;
            ((float4*)wqS)[kk*16 + cq] =
                *(const float4*)(Wq + (size_t)(k0 + kk)*512 + cb*64 + cq*4);
        }
        __syncthreads();

        const float* oS = outS + slice*16*32;
        const float* wS = wqS  + slice*16*64;
#pragma unroll
        for (int kk = 0; kk < 16; kk++){
            float4 o4 = *(const float4*)(oS + kk*32 + b0);
            ull ob0 = pack2(o4.x), ob1 = pack2(o4.y), ob2 = pack2(o4.z), ob3 = pack2(o4.w);
            const ull* w2 = (const ull*)(wS + kk*64 + c0);
#pragma unroll
            for (int cp = 0; cp < 4; cp++){
                ull wv = w2[cp];
                acc2[0*4+cp] = fma2(ob0, wv, acc2[0*4+cp]);
                acc2[1*4+cp] = fma2(ob1, wv, acc2[1*4+cp]);
                acc2[2*4+cp] = fma2(ob2, wv, acc2[2*4+cp]);
                acc2[3*4+cp] = fma2(ob3, wv, acc2[3*4+cp]);
            }
        }
    }
    float* qp = g_qpart + (size_t)(ky*4 + slice) * (B*N);
#pragma unroll
    for (int bb = 0; bb < 4; bb++)
#pragma unroll
        for (int cp = 0; cp < 4; cp++){
            float lo, hi; unpack2(acc2[bb*4+cp], lo, hi);
            int c = cb*64 + c0 + cp*2;
            qp[(b0+bb)*N + c]     = lo;
            qp[(b0+bb)*N + c + 1] = hi;
        }
}

// ---------------- K6: q = sum of 128 partials + b_q (float4) ----------------
__global__ void k6_reduce(const float* __restrict__ bq, float* __restrict__ q){
    int t4 = blockIdx.x * 128 + threadIdx.x;   // [0, 4096)
    int c4 = t4 & 127;
    float4 s = ((const float4*)bq)[c4];
#pragma unroll
    for (int p = 0; p < 128; p++){
        float4 v = ((const float4*)(g_qpart + (size_t)p*(B*N)))[t4];
        s.x += v.x; s.y += v.y; s.z += v.z; s.w += v.w;
    }
    ((float4*)q)[t4] = s;
}

// ---------------- launch ----------------
extern "C" void kernel_launch(void* const* d_in, const int* in_sizes, int n_in,
                              void* d_out, int out_size){
    const float* xv    = (const float*)d_in[0];
    const float* adj   = (const float*)d_in[1];
    const float* Whead = (const float*)d_in[2];
    const float* a1    = (const float*)d_in[3];
    const float* a2    = (const float*)d_in[4];
    const float* Wout  = (const float*)d_in[5];
    const float* a1o   = (const float*)d_in[6];
    const float* a2o   = (const float*)d_in[7];
    const float* Wq    = (const float*)d_in[8];
    const float* bq    = (const float*)d_in[9];
    float* q = (float*)d_out;

    k0_compact<<<B*N/8, 256>>>(adj);
    k1_proj   <<<512, 256>>>(xv, Whead, a1, a2);
    k2_fused  <<<B*N/4, 256>>>(Wout, a1o, a2o);
    k4_outattn<<<B*N/8, 256>>>();
    k5_qgemm  <<<dim3(8, 32), 256>>>(Wq);
    k6_reduce <<<32, 128>>>(bq, q);
}